// round 15
// baseline (speedup 1.0000x reference)
#include <cuda_runtime.h>
#include <cuda_fp16.h>

#define W_   128
#define H_   256
#define D_   256
#define NVOX 16777216
#define SD_  32768
#define CH   8                // d-slices per thread
#define LAMB 0.01f
#define FULLM 0xffffffffu

__device__ unsigned int g_zpk[NVOX];   // {z0,z1} packed half2 per voxel
__device__ __half       g_z2[NVOX];

struct ZP { float a[4]; float b[4]; };

__device__ __forceinline__ float4 ld4(const float* p, int idx) { return *(const float4*)(p + idx); }

__device__ __forceinline__ ZP unpk(uint4 raw) {
    ZP r; float2 f;
    f = __half22float2(*(const __half2*)&raw.x); r.a[0]=f.x; r.b[0]=f.y;
    f = __half22float2(*(const __half2*)&raw.y); r.a[1]=f.x; r.b[1]=f.y;
    f = __half22float2(*(const __half2*)&raw.z); r.a[2]=f.x; r.b[2]=f.y;
    f = __half22float2(*(const __half2*)&raw.w); r.a[3]=f.x; r.b[3]=f.y;
    return r;
}
__device__ __forceinline__ ZP ldpk(const unsigned int* p, int idx) {
    return unpk(*(const uint4*)(p + idx));
}
__device__ __forceinline__ void stpk(unsigned int* p, int idx,
                                     const float* a, const float* b) {
    uint4 raw;
    __half2 h;
    h = __floats2half2_rn(a[0], b[0]); raw.x = *(const unsigned int*)&h;
    h = __floats2half2_rn(a[1], b[1]); raw.y = *(const unsigned int*)&h;
    h = __floats2half2_rn(a[2], b[2]); raw.z = *(const unsigned int*)&h;
    h = __floats2half2_rn(a[3], b[3]); raw.w = *(const unsigned int*)&h;
    *(uint4*)(p + idx) = raw;
}
__device__ __forceinline__ void ldh4(const __half* p, int idx, float* v) {
    uint2 raw = *(const uint2*)(p + idx);
    float2 f;
    f = __half22float2(*(const __half2*)&raw.x); v[0]=f.x; v[1]=f.y;
    f = __half22float2(*(const __half2*)&raw.y); v[2]=f.x; v[3]=f.y;
}
__device__ __forceinline__ void sth4(__half* p, int idx, const float* v) {
    uint2 raw;
    __half2 h;
    h = __floats2half2_rn(v[0], v[1]); raw.x = *(const unsigned int*)&h;
    h = __floats2half2_rn(v[2], v[3]); raw.y = *(const unsigned int*)&h;
    *(uint2*)(p + idx) = raw;
}

__device__ __forceinline__ float zf(float t, float s) { return t - LAMB * (t - s); }
__device__ __forceinline__ float clip(float x, float sg) { return fminf(fmaxf(x, -sg), sg); }

// FAST=true assumes nt==0 everywhere: dualu == clip (bitwise-identical result).
template <bool FAST>
__device__ __forceinline__ float dualuT(float p, float dz, float sg, float nt) {
    float pn = clip(p - dz, sg);
    if (FAST) return pn;
    return pn + nt * (pn - p);
}
template <bool FAST>
__device__ __forceinline__ float chain2T(float dz0, float dz1, float sg, float nt0, float nt1) {
    return dualuT<FAST>(dualuT<FAST>(0.f, dz0, sg, nt0), dz1, sg, nt1);
}
template <bool FAST>
__device__ __forceinline__ float chain3T(float dz0, float dz1, float dz2,
                                         float sg, float nt0, float nt1, float nt2) {
    return dualuT<FAST>(dualuT<FAST>(dualuT<FAST>(0.f, dz0, sg, nt0), dz1, sg, nt1), dz2, sg, nt2);
}

// Decode warp -> (b, d0, h); lane covers w = 4*lane .. 4*lane+3
__device__ __forceinline__ int base_idx(int& h, int& d0) {
    int warp = (blockIdx.x * blockDim.x + threadIdx.x) >> 5;
    int lane = threadIdx.x & 31;
    h = warp & (H_ - 1);
    int dchunk = (warp >> 8) & 31;
    int b = warp >> 13;
    d0 = dchunk * CH;
    return ((b * D_ + d0) * H_ + h) * W_ + (lane << 2);
}

// ---------------- cascade 0 ----------------
template <bool FAST>
__device__ __forceinline__ void c0_body(
    const float* __restrict__ image, const float* __restrict__ sino,
    float sg0, float sg1, float sg2, float sg3, float nt0,
    unsigned int* __restrict__ wzpk,
    float* __restrict__ tout, float* __restrict__ out0)
{
    int h, d0;
    int idx0 = base_idx(h, d0);
    int lane = threadIdx.x & 31;
    bool hhi = (h < H_ - 1), hlo = (h > 0);

    float4 tc = ld4(image, idx0);
    float4 sc = ld4(sino, idx0);
    float zc[4] = { zf(tc.x, sc.x), zf(tc.y, sc.y), zf(tc.z, sc.z), zf(tc.w, sc.w) };

    float pem[4] = {0.f, 0.f, 0.f, 0.f};
    if (d0 > 0) {
        float4 a = ld4(image, idx0 - SD_), bb = ld4(sino, idx0 - SD_);
        float zm[4] = { zf(a.x,bb.x), zf(a.y,bb.y), zf(a.z,bb.z), zf(a.w,bb.w) };
#pragma unroll
        for (int j = 0; j < 4; j++) pem[j] = dualuT<FAST>(0.f, zc[j] - zm[j], sg0, nt0);
    }

#pragma unroll 2
    for (int dd = 0; dd < CH; dd++) {
        int idx = idx0 + dd * SD_;
        int d = d0 + dd;

        float4 tn = tc, sn = sc;
        float zn[4];
        if (d < D_ - 1) { tn = ld4(image, idx + SD_); sn = ld4(sino, idx + SD_); }
        zn[0] = zf(tn.x, sn.x); zn[1] = zf(tn.y, sn.y);
        zn[2] = zf(tn.z, sn.z); zn[3] = zf(tn.w, sn.w);
        if (d == D_ - 1) { zn[0]=zc[0]; zn[1]=zc[1]; zn[2]=zc[2]; zn[3]=zc[3]; }

        float zhp[4], zhm[4];
        if (hhi) { float4 a = ld4(image, idx + W_), bb = ld4(sino, idx + W_);
                   zhp[0]=zf(a.x,bb.x); zhp[1]=zf(a.y,bb.y); zhp[2]=zf(a.z,bb.z); zhp[3]=zf(a.w,bb.w); }
        else     { zhp[0]=zc[0]; zhp[1]=zc[1]; zhp[2]=zc[2]; zhp[3]=zc[3]; }
        if (hlo) { float4 a = ld4(image, idx - W_), bb = ld4(sino, idx - W_);
                   zhm[0]=zf(a.x,bb.x); zhm[1]=zf(a.y,bb.y); zhm[2]=zf(a.z,bb.z); zhm[3]=zf(a.w,bb.w); }
        else     { zhm[0]=zc[0]; zhm[1]=zc[1]; zhm[2]=zc[2]; zhm[3]=zc[3]; }

        float o[4], pe[4];
#pragma unroll
        for (int j = 0; j < 4; j++) {
            pe[j] = dualuT<FAST>(0.f, zn[j] - zc[j], sg0, nt0);
            float qe  = dualuT<FAST>(0.f, zhp[j] - zc[j], sg1, nt0);
            float qem = dualuT<FAST>(0.f, zc[j] - zhm[j], sg1, nt0);
            o[j] = clip(zc[j], sg3) + pem[j] - pe[j] + qem - qe;
        }
        {
            float znx = __shfl_down_sync(FULLM, zc[0], 1);
            if (lane == 31) znx = zc[3];
            float s[4];
            s[0] = dualuT<FAST>(0.f, zc[1] - zc[0], sg2, nt0);
            s[1] = dualuT<FAST>(0.f, zc[2] - zc[1], sg2, nt0);
            s[2] = dualuT<FAST>(0.f, zc[3] - zc[2], sg2, nt0);
            s[3] = dualuT<FAST>(0.f, znx   - zc[3], sg2, nt0);
            float sem = __shfl_up_sync(FULLM, s[3], 1);
            o[0] += ((lane > 0) ? sem : 0.f) - s[0];
            o[1] += s[0] - s[1];
            o[2] += s[1] - s[2];
            o[3] += s[2] - s[3];
        }

        *(float4*)(tout + idx) = make_float4(o[0], o[1], o[2], o[3]);
        *(float4*)(out0 + idx) = tc;
        float z1v[4] = { zf(o[0], sc.x), zf(o[1], sc.y), zf(o[2], sc.z), zf(o[3], sc.w) };
        stpk(wzpk, idx, zc, z1v);

#pragma unroll
        for (int j = 0; j < 4; j++) { pem[j] = pe[j]; zc[j] = zn[j]; }
        tc = tn; sc = sn;
    }
}

__global__ __launch_bounds__(256, 5)
void dtv_c0(const float* __restrict__ image, const float* __restrict__ sino,
            const float* __restrict__ sig, const float* __restrict__ ntp,
            unsigned int* __restrict__ wzpk,
            float* __restrict__ tout, float* __restrict__ out0)
{
    float sg0 = __ldg(sig+0), sg1 = __ldg(sig+1), sg2 = __ldg(sig+2), sg3 = __ldg(sig+3);
    float nt0 = __ldg(ntp + 0);
    if (nt0 == 0.f)
        c0_body<true >(image, sino, sg0, sg1, sg2, sg3, 0.f, wzpk, tout, out0);
    else
        c0_body<false>(image, sino, sg0, sg1, sg2, sg3, nt0, wzpk, tout, out0);
}

// ---------------- cascade 1 ----------------
template <bool FAST>
__device__ __forceinline__ void c1_body(
    const unsigned int* __restrict__ zpk, const float* __restrict__ sino,
    float sg0, float sg1, float sg2, float sg3, float nt0, float nt1,
    __half* __restrict__ wz2, float* __restrict__ tout)
{
    int h, d0;
    int idx0 = base_idx(h, d0);
    int lane = threadIdx.x & 31;
    bool hhi = (h < H_ - 1), hlo = (h > 0);

    ZP zc = ldpk(zpk, idx0);
    float pem[4] = {0.f, 0.f, 0.f, 0.f};
    if (d0 > 0) {
        ZP zm = ldpk(zpk, idx0 - SD_);
#pragma unroll
        for (int j = 0; j < 4; j++)
            pem[j] = chain2T<FAST>(zc.a[j] - zm.a[j], zc.b[j] - zm.b[j], sg0, nt0, nt1);
    }

#pragma unroll 2
    for (int dd = 0; dd < CH; dd++) {
        int idx = idx0 + dd * SD_;
        int d = d0 + dd;

        ZP zn = (d < D_ - 1) ? ldpk(zpk, idx + SD_) : zc;
        ZP zhp = hhi ? ldpk(zpk, idx + W_) : zc;
        ZP zhm = hlo ? ldpk(zpk, idx - W_) : zc;

        float o[4], pe[4];
#pragma unroll
        for (int j = 0; j < 4; j++) {
            pe[j] = chain2T<FAST>(zn.a[j] - zc.a[j],  zn.b[j] - zc.b[j],  sg0, nt0, nt1);
            float qe  = chain2T<FAST>(zhp.a[j] - zc.a[j], zhp.b[j] - zc.b[j], sg1, nt0, nt1);
            float qem = chain2T<FAST>(zc.a[j] - zhm.a[j], zc.b[j] - zhm.b[j], sg1, nt0, nt1);
            o[j] = clip(zc.b[j], sg3) + pem[j] - pe[j] + qem - qe;
        }
        {
            float zax = __shfl_down_sync(FULLM, zc.a[0], 1);
            float zbx = __shfl_down_sync(FULLM, zc.b[0], 1);
            if (lane == 31) { zax = zc.a[3]; zbx = zc.b[3]; }
            float s[4];
            s[0] = chain2T<FAST>(zc.a[1] - zc.a[0], zc.b[1] - zc.b[0], sg2, nt0, nt1);
            s[1] = chain2T<FAST>(zc.a[2] - zc.a[1], zc.b[2] - zc.b[1], sg2, nt0, nt1);
            s[2] = chain2T<FAST>(zc.a[3] - zc.a[2], zc.b[3] - zc.b[2], sg2, nt0, nt1);
            s[3] = chain2T<FAST>(zax     - zc.a[3], zbx     - zc.b[3], sg2, nt0, nt1);
            float sem = __shfl_up_sync(FULLM, s[3], 1);
            o[0] += ((lane > 0) ? sem : 0.f) - s[0];
            o[1] += s[0] - s[1];
            o[2] += s[1] - s[2];
            o[3] += s[2] - s[3];
        }

        *(float4*)(tout + idx) = make_float4(o[0], o[1], o[2], o[3]);
        float4 s4 = ld4(sino, idx);
        float z2v[4] = { zf(o[0], s4.x), zf(o[1], s4.y), zf(o[2], s4.z), zf(o[3], s4.w) };
        sth4(wz2, idx, z2v);

#pragma unroll
        for (int j = 0; j < 4; j++) pem[j] = pe[j];
        zc = zn;
    }
}

__global__ __launch_bounds__(256, 5)
void dtv_c1(const unsigned int* __restrict__ zpk, const float* __restrict__ sino,
            const float* __restrict__ sig, const float* __restrict__ ntp,
            __half* __restrict__ wz2, float* __restrict__ tout)
{
    float sg0 = __ldg(sig+0), sg1 = __ldg(sig+1), sg2 = __ldg(sig+2), sg3 = __ldg(sig+3);
    float nt0 = __ldg(ntp + 0), nt1 = __ldg(ntp + 1);
    if (nt0 == 0.f && nt1 == 0.f)
        c1_body<true >(zpk, sino, sg0, sg1, sg2, sg3, 0.f, 0.f, wz2, tout);
    else
        c1_body<false>(zpk, sino, sg0, sg1, sg2, sg3, nt0, nt1, wz2, tout);
}

// ---------------- cascade 2 ----------------
template <bool FAST>
__device__ __forceinline__ void c2_body(
    const unsigned int* __restrict__ zpk, const __half* __restrict__ z2,
    float sg0, float sg1, float sg2, float sg3,
    float nt0, float nt1, float nt2,
    float* __restrict__ tout)
{
    int h, d0;
    int idx0 = base_idx(h, d0);
    int lane = threadIdx.x & 31;
    bool hhi = (h < H_ - 1), hlo = (h > 0);

    ZP zc = ldpk(zpk, idx0);
    float cc[4];
    ldh4(z2, idx0, cc);
    float pem[4] = {0.f, 0.f, 0.f, 0.f};
    if (d0 > 0) {
        ZP zm = ldpk(zpk, idx0 - SD_);
        float cm[4];
        ldh4(z2, idx0 - SD_, cm);
#pragma unroll
        for (int j = 0; j < 4; j++)
            pem[j] = chain3T<FAST>(zc.a[j]-zm.a[j], zc.b[j]-zm.b[j], cc[j]-cm[j], sg0, nt0, nt1, nt2);
    }

#pragma unroll 2
    for (int dd = 0; dd < CH; dd++) {
        int idx = idx0 + dd * SD_;
        int d = d0 + dd;

        ZP zn = zc;
        float cn[4] = { cc[0], cc[1], cc[2], cc[3] };
        if (d < D_ - 1) { zn = ldpk(zpk, idx + SD_); ldh4(z2, idx + SD_, cn); }

        ZP zhp = zc, zhm = zc;
        float chp[4] = { cc[0], cc[1], cc[2], cc[3] };
        float chm[4] = { cc[0], cc[1], cc[2], cc[3] };
        if (hhi) { zhp = ldpk(zpk, idx + W_); ldh4(z2, idx + W_, chp); }
        if (hlo) { zhm = ldpk(zpk, idx - W_); ldh4(z2, idx - W_, chm); }

        float o[4], pe[4];
#pragma unroll
        for (int j = 0; j < 4; j++) {
            pe[j] = chain3T<FAST>(zn.a[j]-zc.a[j],  zn.b[j]-zc.b[j],  cn[j]-cc[j],  sg0, nt0, nt1, nt2);
            float qe  = chain3T<FAST>(zhp.a[j]-zc.a[j], zhp.b[j]-zc.b[j], chp[j]-cc[j], sg1, nt0, nt1, nt2);
            float qem = chain3T<FAST>(zc.a[j]-zhm.a[j], zc.b[j]-zhm.b[j], cc[j]-chm[j], sg1, nt0, nt1, nt2);
            o[j] = clip(cc[j], sg3) + pem[j] - pe[j] + qem - qe;
        }
        {
            float zax = __shfl_down_sync(FULLM, zc.a[0], 1);
            float zbx = __shfl_down_sync(FULLM, zc.b[0], 1);
            float zcx = __shfl_down_sync(FULLM, cc[0],   1);
            if (lane == 31) { zax = zc.a[3]; zbx = zc.b[3]; zcx = cc[3]; }
            float s[4];
            s[0] = chain3T<FAST>(zc.a[1]-zc.a[0], zc.b[1]-zc.b[0], cc[1]-cc[0], sg2, nt0, nt1, nt2);
            s[1] = chain3T<FAST>(zc.a[2]-zc.a[1], zc.b[2]-zc.b[1], cc[2]-cc[1], sg2, nt0, nt1, nt2);
            s[2] = chain3T<FAST>(zc.a[3]-zc.a[2], zc.b[3]-zc.b[2], cc[3]-cc[2], sg2, nt0, nt1, nt2);
            s[3] = chain3T<FAST>(zax-zc.a[3],     zbx-zc.b[3],     zcx-cc[3],   sg2, nt0, nt1, nt2);
            float sem = __shfl_up_sync(FULLM, s[3], 1);
            o[0] += ((lane > 0) ? sem : 0.f) - s[0];
            o[1] += s[0] - s[1];
            o[2] += s[1] - s[2];
            o[3] += s[2] - s[3];
        }

        *(float4*)(tout + idx) = make_float4(o[0], o[1], o[2], o[3]);

#pragma unroll
        for (int j = 0; j < 4; j++) { pem[j] = pe[j]; cc[j] = cn[j]; }
        zc = zn;
    }
}

__global__ __launch_bounds__(256, 5)
void dtv_c2(const unsigned int* __restrict__ zpk, const __half* __restrict__ z2,
            const float* __restrict__ sig, const float* __restrict__ ntp,
            float* __restrict__ tout)
{
    float sg0 = __ldg(sig+0), sg1 = __ldg(sig+1), sg2 = __ldg(sig+2), sg3 = __ldg(sig+3);
    float nt0 = __ldg(ntp + 0), nt1 = __ldg(ntp + 1), nt2 = __ldg(ntp + 2);
    if (nt0 == 0.f && nt1 == 0.f && nt2 == 0.f)
        c2_body<true >(zpk, z2, sg0, sg1, sg2, sg3, 0.f, 0.f, 0.f, tout);
    else
        c2_body<false>(zpk, z2, sg0, sg1, sg2, sg3, nt0, nt1, nt2, tout);
}

extern "C" void kernel_launch(void* const* d_in, const int* in_sizes, int n_in,
                              void* d_out, int out_size)
{
    const float* image = nullptr;
    const float* sino  = nullptr;
    const float* sigma = nullptr;
    const float* ntv   = nullptr;
    for (int i = 0; i < n_in; i++) {
        if (in_sizes[i] == 4) sigma = (const float*)d_in[i];
        else if (in_sizes[i] == 3) ntv = (const float*)d_in[i];
        else if (!image) image = (const float*)d_in[i];
        else if (!sino)  sino  = (const float*)d_in[i];
    }
    float* out = (float*)d_out;

    unsigned int* zpk;
    __half* z2a;
    cudaGetSymbolAddress((void**)&zpk, g_zpk);
    cudaGetSymbolAddress((void**)&z2a, g_z2);

    // threads = NVOX/4/CH = 524288 -> 2048 blocks of 256
    dim3 grid(NVOX / 4 / CH / 256), block(256);

    dtv_c0<<<grid, block>>>(image, sino, sigma, ntv, zpk, out + 1u * NVOX, out);
    dtv_c1<<<grid, block>>>(zpk, sino, sigma, ntv, z2a, out + 2u * NVOX);
    dtv_c2<<<grid, block>>>(zpk, z2a, sigma, ntv, out + 3u * NVOX);
}

// round 16
// speedup vs baseline: 1.1435x; 1.1435x over previous
#include <cuda_runtime.h>
#include <cuda_fp16.h>

#define W_   128
#define H_   256
#define D_   256
#define NVOX 16777216
#define SD_  32768
#define CH   4                // d-slices per thread (4 -> 4096 blocks, ~7 waves)
#define NCHK 64               // D_/CH
#define LAMB 0.01f
#define FULLM 0xffffffffu

__device__ unsigned int g_zpk[NVOX];   // {z0,z1} packed half2 per voxel
__device__ __half       g_z2[NVOX];

struct ZP { float a[4]; float b[4]; };

__device__ __forceinline__ float4 ld4(const float* p, int idx) { return *(const float4*)(p + idx); }

__device__ __forceinline__ ZP unpk(uint4 raw) {
    ZP r; float2 f;
    f = __half22float2(*(const __half2*)&raw.x); r.a[0]=f.x; r.b[0]=f.y;
    f = __half22float2(*(const __half2*)&raw.y); r.a[1]=f.x; r.b[1]=f.y;
    f = __half22float2(*(const __half2*)&raw.z); r.a[2]=f.x; r.b[2]=f.y;
    f = __half22float2(*(const __half2*)&raw.w); r.a[3]=f.x; r.b[3]=f.y;
    return r;
}
__device__ __forceinline__ ZP ldpk(const unsigned int* p, int idx) {
    return unpk(*(const uint4*)(p + idx));
}
__device__ __forceinline__ void stpk(unsigned int* p, int idx,
                                     const float* a, const float* b) {
    uint4 raw;
    __half2 h;
    h = __floats2half2_rn(a[0], b[0]); raw.x = *(const unsigned int*)&h;
    h = __floats2half2_rn(a[1], b[1]); raw.y = *(const unsigned int*)&h;
    h = __floats2half2_rn(a[2], b[2]); raw.z = *(const unsigned int*)&h;
    h = __floats2half2_rn(a[3], b[3]); raw.w = *(const unsigned int*)&h;
    *(uint4*)(p + idx) = raw;
}
__device__ __forceinline__ void ldh4(const __half* p, int idx, float* v) {
    uint2 raw = *(const uint2*)(p + idx);
    float2 f;
    f = __half22float2(*(const __half2*)&raw.x); v[0]=f.x; v[1]=f.y;
    f = __half22float2(*(const __half2*)&raw.y); v[2]=f.x; v[3]=f.y;
}
__device__ __forceinline__ void sth4(__half* p, int idx, const float* v) {
    uint2 raw;
    __half2 h;
    h = __floats2half2_rn(v[0], v[1]); raw.x = *(const unsigned int*)&h;
    h = __floats2half2_rn(v[2], v[3]); raw.y = *(const unsigned int*)&h;
    *(uint2*)(p + idx) = raw;
}

__device__ __forceinline__ float zf(float t, float s) { return t - LAMB * (t - s); }
__device__ __forceinline__ float clip(float x, float sg) { return fminf(fmaxf(x, -sg), sg); }

// FAST=true assumes nt==0 everywhere: dualu == clip (bitwise-identical result).
template <bool FAST>
__device__ __forceinline__ float dualuT(float p, float dz, float sg, float nt) {
    float pn = clip(p - dz, sg);
    if (FAST) return pn;
    return pn + nt * (pn - p);
}
template <bool FAST>
__device__ __forceinline__ float chain2T(float dz0, float dz1, float sg, float nt0, float nt1) {
    return dualuT<FAST>(dualuT<FAST>(0.f, dz0, sg, nt0), dz1, sg, nt1);
}
template <bool FAST>
__device__ __forceinline__ float chain3T(float dz0, float dz1, float dz2,
                                         float sg, float nt0, float nt1, float nt2) {
    return dualuT<FAST>(dualuT<FAST>(dualuT<FAST>(0.f, dz0, sg, nt0), dz1, sg, nt1), dz2, sg, nt2);
}

// Decode warp -> (b, d0, h); lane covers w = 4*lane .. 4*lane+3
__device__ __forceinline__ int base_idx(int& h, int& d0) {
    int warp = (blockIdx.x * blockDim.x + threadIdx.x) >> 5;
    int lane = threadIdx.x & 31;
    h = warp & (H_ - 1);
    int dchunk = (warp >> 8) & (NCHK - 1);
    int b = warp >> 14;                    // 8 bits h + 6 bits dchunk
    d0 = dchunk * CH;
    return ((b * D_ + d0) * H_ + h) * W_ + (lane << 2);
}

// ---------------- cascade 0 ----------------
template <bool FAST>
__device__ __forceinline__ void c0_body(
    const float* __restrict__ image, const float* __restrict__ sino,
    float sg0, float sg1, float sg2, float sg3, float nt0,
    unsigned int* __restrict__ wzpk,
    float* __restrict__ tout, float* __restrict__ out0)
{
    int h, d0;
    int idx0 = base_idx(h, d0);
    int lane = threadIdx.x & 31;
    bool hhi = (h < H_ - 1), hlo = (h > 0);

    float4 tc = ld4(image, idx0);
    float4 sc = ld4(sino, idx0);
    float zc[4] = { zf(tc.x, sc.x), zf(tc.y, sc.y), zf(tc.z, sc.z), zf(tc.w, sc.w) };

    float pem[4] = {0.f, 0.f, 0.f, 0.f};
    if (d0 > 0) {
        float4 a = ld4(image, idx0 - SD_), bb = ld4(sino, idx0 - SD_);
        float zm[4] = { zf(a.x,bb.x), zf(a.y,bb.y), zf(a.z,bb.z), zf(a.w,bb.w) };
#pragma unroll
        for (int j = 0; j < 4; j++) pem[j] = dualuT<FAST>(0.f, zc[j] - zm[j], sg0, nt0);
    }

#pragma unroll 2
    for (int dd = 0; dd < CH; dd++) {
        int idx = idx0 + dd * SD_;
        int d = d0 + dd;

        float4 tn = tc, sn = sc;
        float zn[4];
        if (d < D_ - 1) { tn = ld4(image, idx + SD_); sn = ld4(sino, idx + SD_); }
        zn[0] = zf(tn.x, sn.x); zn[1] = zf(tn.y, sn.y);
        zn[2] = zf(tn.z, sn.z); zn[3] = zf(tn.w, sn.w);
        if (d == D_ - 1) { zn[0]=zc[0]; zn[1]=zc[1]; zn[2]=zc[2]; zn[3]=zc[3]; }

        float zhp[4], zhm[4];
        if (hhi) { float4 a = ld4(image, idx + W_), bb = ld4(sino, idx + W_);
                   zhp[0]=zf(a.x,bb.x); zhp[1]=zf(a.y,bb.y); zhp[2]=zf(a.z,bb.z); zhp[3]=zf(a.w,bb.w); }
        else     { zhp[0]=zc[0]; zhp[1]=zc[1]; zhp[2]=zc[2]; zhp[3]=zc[3]; }
        if (hlo) { float4 a = ld4(image, idx - W_), bb = ld4(sino, idx - W_);
                   zhm[0]=zf(a.x,bb.x); zhm[1]=zf(a.y,bb.y); zhm[2]=zf(a.z,bb.z); zhm[3]=zf(a.w,bb.w); }
        else     { zhm[0]=zc[0]; zhm[1]=zc[1]; zhm[2]=zc[2]; zhm[3]=zc[3]; }

        float o[4], pe[4];
#pragma unroll
        for (int j = 0; j < 4; j++) {
            pe[j] = dualuT<FAST>(0.f, zn[j] - zc[j], sg0, nt0);
            float qe  = dualuT<FAST>(0.f, zhp[j] - zc[j], sg1, nt0);
            float qem = dualuT<FAST>(0.f, zc[j] - zhm[j], sg1, nt0);
            o[j] = clip(zc[j], sg3) + pem[j] - pe[j] + qem - qe;
        }
        {
            float znx = __shfl_down_sync(FULLM, zc[0], 1);
            if (lane == 31) znx = zc[3];
            float s[4];
            s[0] = dualuT<FAST>(0.f, zc[1] - zc[0], sg2, nt0);
            s[1] = dualuT<FAST>(0.f, zc[2] - zc[1], sg2, nt0);
            s[2] = dualuT<FAST>(0.f, zc[3] - zc[2], sg2, nt0);
            s[3] = dualuT<FAST>(0.f, znx   - zc[3], sg2, nt0);
            float sem = __shfl_up_sync(FULLM, s[3], 1);
            o[0] += ((lane > 0) ? sem : 0.f) - s[0];
            o[1] += s[0] - s[1];
            o[2] += s[1] - s[2];
            o[3] += s[2] - s[3];
        }

        *(float4*)(tout + idx) = make_float4(o[0], o[1], o[2], o[3]);
        *(float4*)(out0 + idx) = tc;
        float z1v[4] = { zf(o[0], sc.x), zf(o[1], sc.y), zf(o[2], sc.z), zf(o[3], sc.w) };
        stpk(wzpk, idx, zc, z1v);

#pragma unroll
        for (int j = 0; j < 4; j++) { pem[j] = pe[j]; zc[j] = zn[j]; }
        tc = tn; sc = sn;
    }
}

__global__ __launch_bounds__(256)
void dtv_c0(const float* __restrict__ image, const float* __restrict__ sino,
            const float* __restrict__ sig, const float* __restrict__ ntp,
            unsigned int* __restrict__ wzpk,
            float* __restrict__ tout, float* __restrict__ out0)
{
    float sg0 = __ldg(sig+0), sg1 = __ldg(sig+1), sg2 = __ldg(sig+2), sg3 = __ldg(sig+3);
    float nt0 = __ldg(ntp + 0);
    if (nt0 == 0.f)
        c0_body<true >(image, sino, sg0, sg1, sg2, sg3, 0.f, wzpk, tout, out0);
    else
        c0_body<false>(image, sino, sg0, sg1, sg2, sg3, nt0, wzpk, tout, out0);
}

// ---------------- cascade 1 ----------------
template <bool FAST>
__device__ __forceinline__ void c1_body(
    const unsigned int* __restrict__ zpk, const float* __restrict__ sino,
    float sg0, float sg1, float sg2, float sg3, float nt0, float nt1,
    __half* __restrict__ wz2, float* __restrict__ tout)
{
    int h, d0;
    int idx0 = base_idx(h, d0);
    int lane = threadIdx.x & 31;
    bool hhi = (h < H_ - 1), hlo = (h > 0);

    ZP zc = ldpk(zpk, idx0);
    float pem[4] = {0.f, 0.f, 0.f, 0.f};
    if (d0 > 0) {
        ZP zm = ldpk(zpk, idx0 - SD_);
#pragma unroll
        for (int j = 0; j < 4; j++)
            pem[j] = chain2T<FAST>(zc.a[j] - zm.a[j], zc.b[j] - zm.b[j], sg0, nt0, nt1);
    }

#pragma unroll 2
    for (int dd = 0; dd < CH; dd++) {
        int idx = idx0 + dd * SD_;
        int d = d0 + dd;

        ZP zn = (d < D_ - 1) ? ldpk(zpk, idx + SD_) : zc;
        ZP zhp = hhi ? ldpk(zpk, idx + W_) : zc;
        ZP zhm = hlo ? ldpk(zpk, idx - W_) : zc;

        float o[4], pe[4];
#pragma unroll
        for (int j = 0; j < 4; j++) {
            pe[j] = chain2T<FAST>(zn.a[j] - zc.a[j],  zn.b[j] - zc.b[j],  sg0, nt0, nt1);
            float qe  = chain2T<FAST>(zhp.a[j] - zc.a[j], zhp.b[j] - zc.b[j], sg1, nt0, nt1);
            float qem = chain2T<FAST>(zc.a[j] - zhm.a[j], zc.b[j] - zhm.b[j], sg1, nt0, nt1);
            o[j] = clip(zc.b[j], sg3) + pem[j] - pe[j] + qem - qe;
        }
        {
            float zax = __shfl_down_sync(FULLM, zc.a[0], 1);
            float zbx = __shfl_down_sync(FULLM, zc.b[0], 1);
            if (lane == 31) { zax = zc.a[3]; zbx = zc.b[3]; }
            float s[4];
            s[0] = chain2T<FAST>(zc.a[1] - zc.a[0], zc.b[1] - zc.b[0], sg2, nt0, nt1);
            s[1] = chain2T<FAST>(zc.a[2] - zc.a[1], zc.b[2] - zc.b[1], sg2, nt0, nt1);
            s[2] = chain2T<FAST>(zc.a[3] - zc.a[2], zc.b[3] - zc.b[2], sg2, nt0, nt1);
            s[3] = chain2T<FAST>(zax     - zc.a[3], zbx     - zc.b[3], sg2, nt0, nt1);
            float sem = __shfl_up_sync(FULLM, s[3], 1);
            o[0] += ((lane > 0) ? sem : 0.f) - s[0];
            o[1] += s[0] - s[1];
            o[2] += s[1] - s[2];
            o[3] += s[2] - s[3];
        }

        *(float4*)(tout + idx) = make_float4(o[0], o[1], o[2], o[3]);
        float4 s4 = ld4(sino, idx);
        float z2v[4] = { zf(o[0], s4.x), zf(o[1], s4.y), zf(o[2], s4.z), zf(o[3], s4.w) };
        sth4(wz2, idx, z2v);

#pragma unroll
        for (int j = 0; j < 4; j++) pem[j] = pe[j];
        zc = zn;
    }
}

__global__ __launch_bounds__(256)
void dtv_c1(const unsigned int* __restrict__ zpk, const float* __restrict__ sino,
            const float* __restrict__ sig, const float* __restrict__ ntp,
            __half* __restrict__ wz2, float* __restrict__ tout)
{
    float sg0 = __ldg(sig+0), sg1 = __ldg(sig+1), sg2 = __ldg(sig+2), sg3 = __ldg(sig+3);
    float nt0 = __ldg(ntp + 0), nt1 = __ldg(ntp + 1);
    if (nt0 == 0.f && nt1 == 0.f)
        c1_body<true >(zpk, sino, sg0, sg1, sg2, sg3, 0.f, 0.f, wz2, tout);
    else
        c1_body<false>(zpk, sino, sg0, sg1, sg2, sg3, nt0, nt1, wz2, tout);
}

// ---------------- cascade 2 ----------------
template <bool FAST>
__device__ __forceinline__ void c2_body(
    const unsigned int* __restrict__ zpk, const __half* __restrict__ z2,
    float sg0, float sg1, float sg2, float sg3,
    float nt0, float nt1, float nt2,
    float* __restrict__ tout)
{
    int h, d0;
    int idx0 = base_idx(h, d0);
    int lane = threadIdx.x & 31;
    bool hhi = (h < H_ - 1), hlo = (h > 0);

    ZP zc = ldpk(zpk, idx0);
    float cc[4];
    ldh4(z2, idx0, cc);
    float pem[4] = {0.f, 0.f, 0.f, 0.f};
    if (d0 > 0) {
        ZP zm = ldpk(zpk, idx0 - SD_);
        float cm[4];
        ldh4(z2, idx0 - SD_, cm);
#pragma unroll
        for (int j = 0; j < 4; j++)
            pem[j] = chain3T<FAST>(zc.a[j]-zm.a[j], zc.b[j]-zm.b[j], cc[j]-cm[j], sg0, nt0, nt1, nt2);
    }

#pragma unroll 2
    for (int dd = 0; dd < CH; dd++) {
        int idx = idx0 + dd * SD_;
        int d = d0 + dd;

        ZP zn = zc;
        float cn[4] = { cc[0], cc[1], cc[2], cc[3] };
        if (d < D_ - 1) { zn = ldpk(zpk, idx + SD_); ldh4(z2, idx + SD_, cn); }

        ZP zhp = zc, zhm = zc;
        float chp[4] = { cc[0], cc[1], cc[2], cc[3] };
        float chm[4] = { cc[0], cc[1], cc[2], cc[3] };
        if (hhi) { zhp = ldpk(zpk, idx + W_); ldh4(z2, idx + W_, chp); }
        if (hlo) { zhm = ldpk(zpk, idx - W_); ldh4(z2, idx - W_, chm); }

        float o[4], pe[4];
#pragma unroll
        for (int j = 0; j < 4; j++) {
            pe[j] = chain3T<FAST>(zn.a[j]-zc.a[j],  zn.b[j]-zc.b[j],  cn[j]-cc[j],  sg0, nt0, nt1, nt2);
            float qe  = chain3T<FAST>(zhp.a[j]-zc.a[j], zhp.b[j]-zc.b[j], chp[j]-cc[j], sg1, nt0, nt1, nt2);
            float qem = chain3T<FAST>(zc.a[j]-zhm.a[j], zc.b[j]-zhm.b[j], cc[j]-chm[j], sg1, nt0, nt1, nt2);
            o[j] = clip(cc[j], sg3) + pem[j] - pe[j] + qem - qe;
        }
        {
            float zax = __shfl_down_sync(FULLM, zc.a[0], 1);
            float zbx = __shfl_down_sync(FULLM, zc.b[0], 1);
            float zcx = __shfl_down_sync(FULLM, cc[0],   1);
            if (lane == 31) { zax = zc.a[3]; zbx = zc.b[3]; zcx = cc[3]; }
            float s[4];
            s[0] = chain3T<FAST>(zc.a[1]-zc.a[0], zc.b[1]-zc.b[0], cc[1]-cc[0], sg2, nt0, nt1, nt2);
            s[1] = chain3T<FAST>(zc.a[2]-zc.a[1], zc.b[2]-zc.b[1], cc[2]-cc[1], sg2, nt0, nt1, nt2);
            s[2] = chain3T<FAST>(zc.a[3]-zc.a[2], zc.b[3]-zc.b[2], cc[3]-cc[2], sg2, nt0, nt1, nt2);
            s[3] = chain3T<FAST>(zax-zc.a[3],     zbx-zc.b[3],     zcx-cc[3],   sg2, nt0, nt1, nt2);
            float sem = __shfl_up_sync(FULLM, s[3], 1);
            o[0] += ((lane > 0) ? sem : 0.f) - s[0];
            o[1] += s[0] - s[1];
            o[2] += s[1] - s[2];
            o[3] += s[2] - s[3];
        }

        *(float4*)(tout + idx) = make_float4(o[0], o[1], o[2], o[3]);

#pragma unroll
        for (int j = 0; j < 4; j++) { pem[j] = pe[j]; cc[j] = cn[j]; }
        zc = zn;
    }
}

__global__ __launch_bounds__(256)
void dtv_c2(const unsigned int* __restrict__ zpk, const __half* __restrict__ z2,
            const float* __restrict__ sig, const float* __restrict__ ntp,
            float* __restrict__ tout)
{
    float sg0 = __ldg(sig+0), sg1 = __ldg(sig+1), sg2 = __ldg(sig+2), sg3 = __ldg(sig+3);
    float nt0 = __ldg(ntp + 0), nt1 = __ldg(ntp + 1), nt2 = __ldg(ntp + 2);
    if (nt0 == 0.f && nt1 == 0.f && nt2 == 0.f)
        c2_body<true >(zpk, z2, sg0, sg1, sg2, sg3, 0.f, 0.f, 0.f, tout);
    else
        c2_body<false>(zpk, z2, sg0, sg1, sg2, sg3, nt0, nt1, nt2, tout);
}

extern "C" void kernel_launch(void* const* d_in, const int* in_sizes, int n_in,
                              void* d_out, int out_size)
{
    const float* image = nullptr;
    const float* sino  = nullptr;
    const float* sigma = nullptr;
    const float* ntv   = nullptr;
    for (int i = 0; i < n_in; i++) {
        if (in_sizes[i] == 4) sigma = (const float*)d_in[i];
        else if (in_sizes[i] == 3) ntv = (const float*)d_in[i];
        else if (!image) image = (const float*)d_in[i];
        else if (!sino)  sino  = (const float*)d_in[i];
    }
    float* out = (float*)d_out;

    unsigned int* zpk;
    __half* z2a;
    cudaGetSymbolAddress((void**)&zpk, g_zpk);
    cudaGetSymbolAddress((void**)&z2a, g_z2);

    // threads = NVOX/4/CH = 1048576 -> 4096 blocks of 256
    dim3 grid(NVOX / 4 / CH / 256), block(256);

    dtv_c0<<<grid, block>>>(image, sino, sigma, ntv, zpk, out + 1u * NVOX, out);
    dtv_c1<<<grid, block>>>(zpk, sino, sigma, ntv, z2a, out + 2u * NVOX);
    dtv_c2<<<grid, block>>>(zpk, z2a, sigma, ntv, out + 3u * NVOX);
}

// round 17
// speedup vs baseline: 1.1524x; 1.0078x over previous
#include <cuda_runtime.h>
#include <cuda_fp16.h>

#define W_   128
#define H_   256
#define D_   256
#define NVOX 16777216
#define SD_  32768
#define CH   4                // d-slices per thread (4096 blocks)
#define NCHK 64               // D_/CH
#define LAMB 0.01f
#define FULLM 0xffffffffu

__device__ unsigned int g_zpk[NVOX];   // {z0,z1} packed half2 per voxel
__device__ __half       g_z2[NVOX];

struct ZP { float a[4]; float b[4]; };

__device__ __forceinline__ float4 ld4(const float* p, int idx) { return *(const float4*)(p + idx); }

__device__ __forceinline__ ZP unpk(uint4 raw) {
    ZP r; float2 f;
    f = __half22float2(*(const __half2*)&raw.x); r.a[0]=f.x; r.b[0]=f.y;
    f = __half22float2(*(const __half2*)&raw.y); r.a[1]=f.x; r.b[1]=f.y;
    f = __half22float2(*(const __half2*)&raw.z); r.a[2]=f.x; r.b[2]=f.y;
    f = __half22float2(*(const __half2*)&raw.w); r.a[3]=f.x; r.b[3]=f.y;
    return r;
}
__device__ __forceinline__ ZP ldpk(const unsigned int* p, int idx) {
    return unpk(*(const uint4*)(p + idx));
}
__device__ __forceinline__ void stpk(unsigned int* p, int idx,
                                     const float* a, const float* b) {
    uint4 raw;
    __half2 h;
    h = __floats2half2_rn(a[0], b[0]); raw.x = *(const unsigned int*)&h;
    h = __floats2half2_rn(a[1], b[1]); raw.y = *(const unsigned int*)&h;
    h = __floats2half2_rn(a[2], b[2]); raw.z = *(const unsigned int*)&h;
    h = __floats2half2_rn(a[3], b[3]); raw.w = *(const unsigned int*)&h;
    *(uint4*)(p + idx) = raw;
}
__device__ __forceinline__ void ldh4(const __half* p, int idx, float* v) {
    uint2 raw = *(const uint2*)(p + idx);
    float2 f;
    f = __half22float2(*(const __half2*)&raw.x); v[0]=f.x; v[1]=f.y;
    f = __half22float2(*(const __half2*)&raw.y); v[2]=f.x; v[3]=f.y;
}
__device__ __forceinline__ void sth4(__half* p, int idx, const float* v) {
    uint2 raw;
    __half2 h;
    h = __floats2half2_rn(v[0], v[1]); raw.x = *(const unsigned int*)&h;
    h = __floats2half2_rn(v[2], v[3]); raw.y = *(const unsigned int*)&h;
    *(uint2*)(p + idx) = raw;
}

__device__ __forceinline__ float zf(float t, float s) { return t - LAMB * (t - s); }
__device__ __forceinline__ float clip(float x, float sg) { return fminf(fmaxf(x, -sg), sg); }

// FAST=true assumes nt==0 everywhere: dualu == clip (bitwise-identical result).
template <bool FAST>
__device__ __forceinline__ float dualuT(float p, float dz, float sg, float nt) {
    float pn = clip(p - dz, sg);
    if (FAST) return pn;
    return pn + nt * (pn - p);
}
template <bool FAST>
__device__ __forceinline__ float chain2T(float dz0, float dz1, float sg, float nt0, float nt1) {
    return dualuT<FAST>(dualuT<FAST>(0.f, dz0, sg, nt0), dz1, sg, nt1);
}
template <bool FAST>
__device__ __forceinline__ float chain3T(float dz0, float dz1, float dz2,
                                         float sg, float nt0, float nt1, float nt2) {
    return dualuT<FAST>(dualuT<FAST>(dualuT<FAST>(0.f, dz0, sg, nt0), dz1, sg, nt1), dz2, sg, nt2);
}

// Decode warp -> (b, d0, h); lane covers w = 4*lane .. 4*lane+3
__device__ __forceinline__ int base_idx(int& h, int& d0) {
    int warp = (blockIdx.x * blockDim.x + threadIdx.x) >> 5;
    int lane = threadIdx.x & 31;
    h = warp & (H_ - 1);
    int dchunk = (warp >> 8) & (NCHK - 1);
    int b = warp >> 14;
    d0 = dchunk * CH;
    return ((b * D_ + d0) * H_ + h) * W_ + (lane << 2);
}

// ---------------- cascade 0 (no out0 copy here anymore) ----------------
template <bool FAST>
__device__ __forceinline__ void c0_body(
    const float* __restrict__ image, const float* __restrict__ sino,
    float sg0, float sg1, float sg2, float sg3, float nt0,
    unsigned int* __restrict__ wzpk,
    float* __restrict__ tout)
{
    int h, d0;
    int idx0 = base_idx(h, d0);
    int lane = threadIdx.x & 31;
    bool hhi = (h < H_ - 1), hlo = (h > 0);

    float4 tc = ld4(image, idx0);
    float4 sc = ld4(sino, idx0);
    float zc[4] = { zf(tc.x, sc.x), zf(tc.y, sc.y), zf(tc.z, sc.z), zf(tc.w, sc.w) };

    float pem[4] = {0.f, 0.f, 0.f, 0.f};
    if (d0 > 0) {
        float4 a = ld4(image, idx0 - SD_), bb = ld4(sino, idx0 - SD_);
        float zm[4] = { zf(a.x,bb.x), zf(a.y,bb.y), zf(a.z,bb.z), zf(a.w,bb.w) };
#pragma unroll
        for (int j = 0; j < 4; j++) pem[j] = dualuT<FAST>(0.f, zc[j] - zm[j], sg0, nt0);
    }

#pragma unroll
    for (int dd = 0; dd < CH; dd++) {
        int idx = idx0 + dd * SD_;
        int d = d0 + dd;

        float4 tn = tc, sn = sc;
        float zn[4];
        if (d < D_ - 1) { tn = ld4(image, idx + SD_); sn = ld4(sino, idx + SD_); }
        zn[0] = zf(tn.x, sn.x); zn[1] = zf(tn.y, sn.y);
        zn[2] = zf(tn.z, sn.z); zn[3] = zf(tn.w, sn.w);
        if (d == D_ - 1) { zn[0]=zc[0]; zn[1]=zc[1]; zn[2]=zc[2]; zn[3]=zc[3]; }

        float zhp[4], zhm[4];
        if (hhi) { float4 a = ld4(image, idx + W_), bb = ld4(sino, idx + W_);
                   zhp[0]=zf(a.x,bb.x); zhp[1]=zf(a.y,bb.y); zhp[2]=zf(a.z,bb.z); zhp[3]=zf(a.w,bb.w); }
        else     { zhp[0]=zc[0]; zhp[1]=zc[1]; zhp[2]=zc[2]; zhp[3]=zc[3]; }
        if (hlo) { float4 a = ld4(image, idx - W_), bb = ld4(sino, idx - W_);
                   zhm[0]=zf(a.x,bb.x); zhm[1]=zf(a.y,bb.y); zhm[2]=zf(a.z,bb.z); zhm[3]=zf(a.w,bb.w); }
        else     { zhm[0]=zc[0]; zhm[1]=zc[1]; zhm[2]=zc[2]; zhm[3]=zc[3]; }

        float o[4], pe[4];
#pragma unroll
        for (int j = 0; j < 4; j++) {
            pe[j] = dualuT<FAST>(0.f, zn[j] - zc[j], sg0, nt0);
            float qe  = dualuT<FAST>(0.f, zhp[j] - zc[j], sg1, nt0);
            float qem = dualuT<FAST>(0.f, zc[j] - zhm[j], sg1, nt0);
            o[j] = clip(zc[j], sg3) + pem[j] - pe[j] + qem - qe;
        }
        {
            float znx = __shfl_down_sync(FULLM, zc[0], 1);
            if (lane == 31) znx = zc[3];
            float s[4];
            s[0] = dualuT<FAST>(0.f, zc[1] - zc[0], sg2, nt0);
            s[1] = dualuT<FAST>(0.f, zc[2] - zc[1], sg2, nt0);
            s[2] = dualuT<FAST>(0.f, zc[3] - zc[2], sg2, nt0);
            s[3] = dualuT<FAST>(0.f, znx   - zc[3], sg2, nt0);
            float sem = __shfl_up_sync(FULLM, s[3], 1);
            o[0] += ((lane > 0) ? sem : 0.f) - s[0];
            o[1] += s[0] - s[1];
            o[2] += s[1] - s[2];
            o[3] += s[2] - s[3];
        }

        *(float4*)(tout + idx) = make_float4(o[0], o[1], o[2], o[3]);
        float z1v[4] = { zf(o[0], sc.x), zf(o[1], sc.y), zf(o[2], sc.z), zf(o[3], sc.w) };
        stpk(wzpk, idx, zc, z1v);

#pragma unroll
        for (int j = 0; j < 4; j++) { pem[j] = pe[j]; zc[j] = zn[j]; }
        tc = tn; sc = sn;
    }
}

__global__ __launch_bounds__(256)
void dtv_c0(const float* __restrict__ image, const float* __restrict__ sino,
            const float* __restrict__ sig, const float* __restrict__ ntp,
            unsigned int* __restrict__ wzpk,
            float* __restrict__ tout)
{
    float sg0 = __ldg(sig+0), sg1 = __ldg(sig+1), sg2 = __ldg(sig+2), sg3 = __ldg(sig+3);
    float nt0 = __ldg(ntp + 0);
    if (nt0 == 0.f)
        c0_body<true >(image, sino, sg0, sg1, sg2, sg3, 0.f, wzpk, tout);
    else
        c0_body<false>(image, sino, sg0, sg1, sg2, sg3, nt0, wzpk, tout);
}

// ---------------- cascade 1 ----------------
template <bool FAST>
__device__ __forceinline__ void c1_body(
    const unsigned int* __restrict__ zpk, const float* __restrict__ sino,
    float sg0, float sg1, float sg2, float sg3, float nt0, float nt1,
    __half* __restrict__ wz2, float* __restrict__ tout)
{
    int h, d0;
    int idx0 = base_idx(h, d0);
    int lane = threadIdx.x & 31;
    bool hhi = (h < H_ - 1), hlo = (h > 0);

    ZP zc = ldpk(zpk, idx0);
    float pem[4] = {0.f, 0.f, 0.f, 0.f};
    if (d0 > 0) {
        ZP zm = ldpk(zpk, idx0 - SD_);
#pragma unroll
        for (int j = 0; j < 4; j++)
            pem[j] = chain2T<FAST>(zc.a[j] - zm.a[j], zc.b[j] - zm.b[j], sg0, nt0, nt1);
    }

#pragma unroll
    for (int dd = 0; dd < CH; dd++) {
        int idx = idx0 + dd * SD_;
        int d = d0 + dd;

        ZP zn = (d < D_ - 1) ? ldpk(zpk, idx + SD_) : zc;
        ZP zhp = hhi ? ldpk(zpk, idx + W_) : zc;
        ZP zhm = hlo ? ldpk(zpk, idx - W_) : zc;

        float o[4], pe[4];
#pragma unroll
        for (int j = 0; j < 4; j++) {
            pe[j] = chain2T<FAST>(zn.a[j] - zc.a[j],  zn.b[j] - zc.b[j],  sg0, nt0, nt1);
            float qe  = chain2T<FAST>(zhp.a[j] - zc.a[j], zhp.b[j] - zc.b[j], sg1, nt0, nt1);
            float qem = chain2T<FAST>(zc.a[j] - zhm.a[j], zc.b[j] - zhm.b[j], sg1, nt0, nt1);
            o[j] = clip(zc.b[j], sg3) + pem[j] - pe[j] + qem - qe;
        }
        {
            float zax = __shfl_down_sync(FULLM, zc.a[0], 1);
            float zbx = __shfl_down_sync(FULLM, zc.b[0], 1);
            if (lane == 31) { zax = zc.a[3]; zbx = zc.b[3]; }
            float s[4];
            s[0] = chain2T<FAST>(zc.a[1] - zc.a[0], zc.b[1] - zc.b[0], sg2, nt0, nt1);
            s[1] = chain2T<FAST>(zc.a[2] - zc.a[1], zc.b[2] - zc.b[1], sg2, nt0, nt1);
            s[2] = chain2T<FAST>(zc.a[3] - zc.a[2], zc.b[3] - zc.b[2], sg2, nt0, nt1);
            s[3] = chain2T<FAST>(zax     - zc.a[3], zbx     - zc.b[3], sg2, nt0, nt1);
            float sem = __shfl_up_sync(FULLM, s[3], 1);
            o[0] += ((lane > 0) ? sem : 0.f) - s[0];
            o[1] += s[0] - s[1];
            o[2] += s[1] - s[2];
            o[3] += s[2] - s[3];
        }

        *(float4*)(tout + idx) = make_float4(o[0], o[1], o[2], o[3]);
        float4 s4 = ld4(sino, idx);
        float z2v[4] = { zf(o[0], s4.x), zf(o[1], s4.y), zf(o[2], s4.z), zf(o[3], s4.w) };
        sth4(wz2, idx, z2v);

#pragma unroll
        for (int j = 0; j < 4; j++) pem[j] = pe[j];
        zc = zn;
    }
}

__global__ __launch_bounds__(256)
void dtv_c1(const unsigned int* __restrict__ zpk, const float* __restrict__ sino,
            const float* __restrict__ sig, const float* __restrict__ ntp,
            __half* __restrict__ wz2, float* __restrict__ tout)
{
    float sg0 = __ldg(sig+0), sg1 = __ldg(sig+1), sg2 = __ldg(sig+2), sg3 = __ldg(sig+3);
    float nt0 = __ldg(ntp + 0), nt1 = __ldg(ntp + 1);
    if (nt0 == 0.f && nt1 == 0.f)
        c1_body<true >(zpk, sino, sg0, sg1, sg2, sg3, 0.f, 0.f, wz2, tout);
    else
        c1_body<false>(zpk, sino, sg0, sg1, sg2, sg3, nt0, nt1, wz2, tout);
}

// ---------------- cascade 2 (also does out0 = image copy) ----------------
template <bool FAST>
__device__ __forceinline__ void c2_body(
    const unsigned int* __restrict__ zpk, const __half* __restrict__ z2,
    const float* __restrict__ image,
    float sg0, float sg1, float sg2, float sg3,
    float nt0, float nt1, float nt2,
    float* __restrict__ tout, float* __restrict__ out0)
{
    int h, d0;
    int idx0 = base_idx(h, d0);
    int lane = threadIdx.x & 31;
    bool hhi = (h < H_ - 1), hlo = (h > 0);

    ZP zc = ldpk(zpk, idx0);
    float cc[4];
    ldh4(z2, idx0, cc);
    float pem[4] = {0.f, 0.f, 0.f, 0.f};
    if (d0 > 0) {
        ZP zm = ldpk(zpk, idx0 - SD_);
        float cm[4];
        ldh4(z2, idx0 - SD_, cm);
#pragma unroll
        for (int j = 0; j < 4; j++)
            pem[j] = chain3T<FAST>(zc.a[j]-zm.a[j], zc.b[j]-zm.b[j], cc[j]-cm[j], sg0, nt0, nt1, nt2);
    }

#pragma unroll
    for (int dd = 0; dd < CH; dd++) {
        int idx = idx0 + dd * SD_;
        int d = d0 + dd;

        // independent copy stream: out0 = image (uses idle BW; never re-read)
        float4 img = ld4(image, idx);

        ZP zn = zc;
        float cn[4] = { cc[0], cc[1], cc[2], cc[3] };
        if (d < D_ - 1) { zn = ldpk(zpk, idx + SD_); ldh4(z2, idx + SD_, cn); }

        ZP zhp = zc, zhm = zc;
        float chp[4] = { cc[0], cc[1], cc[2], cc[3] };
        float chm[4] = { cc[0], cc[1], cc[2], cc[3] };
        if (hhi) { zhp = ldpk(zpk, idx + W_); ldh4(z2, idx + W_, chp); }
        if (hlo) { zhm = ldpk(zpk, idx - W_); ldh4(z2, idx - W_, chm); }

        float o[4], pe[4];
#pragma unroll
        for (int j = 0; j < 4; j++) {
            pe[j] = chain3T<FAST>(zn.a[j]-zc.a[j],  zn.b[j]-zc.b[j],  cn[j]-cc[j],  sg0, nt0, nt1, nt2);
            float qe  = chain3T<FAST>(zhp.a[j]-zc.a[j], zhp.b[j]-zc.b[j], chp[j]-cc[j], sg1, nt0, nt1, nt2);
            float qem = chain3T<FAST>(zc.a[j]-zhm.a[j], zc.b[j]-zhm.b[j], cc[j]-chm[j], sg1, nt0, nt1, nt2);
            o[j] = clip(cc[j], sg3) + pem[j] - pe[j] + qem - qe;
        }
        {
            float zax = __shfl_down_sync(FULLM, zc.a[0], 1);
            float zbx = __shfl_down_sync(FULLM, zc.b[0], 1);
            float zcx = __shfl_down_sync(FULLM, cc[0],   1);
            if (lane == 31) { zax = zc.a[3]; zbx = zc.b[3]; zcx = cc[3]; }
            float s[4];
            s[0] = chain3T<FAST>(zc.a[1]-zc.a[0], zc.b[1]-zc.b[0], cc[1]-cc[0], sg2, nt0, nt1, nt2);
            s[1] = chain3T<FAST>(zc.a[2]-zc.a[1], zc.b[2]-zc.b[1], cc[2]-cc[1], sg2, nt0, nt1, nt2);
            s[2] = chain3T<FAST>(zc.a[3]-zc.a[2], zc.b[3]-zc.b[2], cc[3]-cc[2], sg2, nt0, nt1, nt2);
            s[3] = chain3T<FAST>(zax-zc.a[3],     zbx-zc.b[3],     zcx-cc[3],   sg2, nt0, nt1, nt2);
            float sem = __shfl_up_sync(FULLM, s[3], 1);
            o[0] += ((lane > 0) ? sem : 0.f) - s[0];
            o[1] += s[0] - s[1];
            o[2] += s[1] - s[2];
            o[3] += s[2] - s[3];
        }

        *(float4*)(tout + idx) = make_float4(o[0], o[1], o[2], o[3]);
        *(float4*)(out0 + idx) = img;

#pragma unroll
        for (int j = 0; j < 4; j++) { pem[j] = pe[j]; cc[j] = cn[j]; }
        zc = zn;
    }
}

__global__ __launch_bounds__(256)
void dtv_c2(const unsigned int* __restrict__ zpk, const __half* __restrict__ z2,
            const float* __restrict__ image,
            const float* __restrict__ sig, const float* __restrict__ ntp,
            float* __restrict__ tout, float* __restrict__ out0)
{
    float sg0 = __ldg(sig+0), sg1 = __ldg(sig+1), sg2 = __ldg(sig+2), sg3 = __ldg(sig+3);
    float nt0 = __ldg(ntp + 0), nt1 = __ldg(ntp + 1), nt2 = __ldg(ntp + 2);
    if (nt0 == 0.f && nt1 == 0.f && nt2 == 0.f)
        c2_body<true >(zpk, z2, image, sg0, sg1, sg2, sg3, 0.f, 0.f, 0.f, tout, out0);
    else
        c2_body<false>(zpk, z2, image, sg0, sg1, sg2, sg3, nt0, nt1, nt2, tout, out0);
}

extern "C" void kernel_launch(void* const* d_in, const int* in_sizes, int n_in,
                              void* d_out, int out_size)
{
    const float* image = nullptr;
    const float* sino  = nullptr;
    const float* sigma = nullptr;
    const float* ntv   = nullptr;
    for (int i = 0; i < n_in; i++) {
        if (in_sizes[i] == 4) sigma = (const float*)d_in[i];
        else if (in_sizes[i] == 3) ntv = (const float*)d_in[i];
        else if (!image) image = (const float*)d_in[i];
        else if (!sino)  sino  = (const float*)d_in[i];
    }
    float* out = (float*)d_out;

    unsigned int* zpk;
    __half* z2a;
    cudaGetSymbolAddress((void**)&zpk, g_zpk);
    cudaGetSymbolAddress((void**)&z2a, g_z2);

    dim3 grid(NVOX / 4 / CH / 256), block(256);   // 4096 blocks

    dtv_c0<<<grid, block>>>(image, sino, sigma, ntv, zpk, out + 1u * NVOX);
    dtv_c1<<<grid, block>>>(zpk, sino, sigma, ntv, z2a, out + 2u * NVOX);
    dtv_c2<<<grid, block>>>(zpk, z2a, image, sigma, ntv, out + 3u * NVOX, out);
}